// round 16
// baseline (speedup 1.0000x reference)
#include <cuda_runtime.h>
#include <cuda_fp16.h>
#include <math.h>

// ---------------------------------------------------------------------------
// SelfAttention_39676907883685 — HMMA fp16 single-precision everywhere,
// 4-stage cp.async ring + 2 CTAs/SM (the previously untested combination:
// deep pipeline AND co-resident CTA; stage is only 20.5KB now).
//
// C[m,n] = alpha * sum_k A[m,k]*B[n,k] (+bias), fp32 accumulate,
// all operands single fp16 (error ~sqrt(5)*2^-12 ~ 5e-4 < 1e-3, measured).
//
// GEMM plan (5 MMA units):
//   GEMM1 kv  = x @ w_qk^T       (2 units) -> fp16 k0u + fp16 v directly
//   GEMM2 s   = k0t @ v^T        (1 unit)  -> fp32 s
//   GEMM4 q   = a @ vT^T         (1 unit)  -> permuted fp16 qp
//   GEMM5 out = qp @ w_dense^T   (1 unit)  -> fp32 out + bias
//
// CTA tile 128x128, 8 warps of 64x32, BK=32.
// ---------------------------------------------------------------------------

typedef unsigned short u16;
typedef unsigned int   u32;

#define BK 32
#define ROWB 80                 // padded smem row bytes -> conflict-free ldsm
#define ARR (128 * ROWB)        // 10240 B per array
#define STAGE (2 * ARR)         // A, B = 20480 B
#define NSTAGE 4
#define SMEM_TOTAL (NSTAGE * STAGE)   // 81920 B ; x2 CTAs = 160KB <= 228KB

// ------------------------------ scratch ------------------------------------
__device__ float g_s [(size_t)4 * 2048 * 2048];

__device__ u16 g_xh [(size_t)8192 * 2048];
__device__ u16 g_wqh[(size_t)4096 * 2048];
__device__ u16 g_wdh[(size_t)2048 * 2048];
__device__ u16 g_k0u[(size_t)4 * 2048 * 2048];   // k0 untransposed (fp16)
__device__ u16 g_vh [(size_t)4 * 2048 * 2048];   // v untransposed  (fp16)
__device__ u16 g_k0t[(size_t)4 * 2048 * 2048];   // k0^T (A of GEMM2)
__device__ u16 g_vth[(size_t)4 * 2048 * 2048];   // v^T  (B of GEMM4)
__device__ u16 g_ah [(size_t)4 * 2048 * 2048];   // softmax(a) fp16
__device__ u16 g_qph[(size_t)4 * 2048 * 2048];   // permuted q fp16

// ------------------------------ helpers ------------------------------------
__device__ __forceinline__ u16 f2h(float x) {
    return __half_as_ushort(__float2half_rn(x));
}
__device__ __forceinline__ u32 packh2(float a, float b) {
    return (u32)f2h(a) | ((u32)f2h(b) << 16);
}

__device__ __forceinline__ void cp16(u32 saddr, const void* gptr) {
    asm volatile("cp.async.cg.shared.global [%0], [%1], 16;\n"
                 :: "r"(saddr), "l"(gptr));
}

__device__ __forceinline__ void ldsm4(u32* r, u32 addr) {
    asm volatile("ldmatrix.sync.aligned.m8n8.x4.shared.b16 {%0,%1,%2,%3}, [%4];\n"
                 : "=r"(r[0]), "=r"(r[1]), "=r"(r[2]), "=r"(r[3]) : "r"(addr));
}

__device__ __forceinline__ void mma16816(float* c, const u32* a, const u32* b) {
    asm volatile(
        "mma.sync.aligned.m16n8k16.row.col.f32.f16.f16.f32 "
        "{%0,%1,%2,%3}, {%4,%5,%6,%7}, {%8,%9}, {%0,%1,%2,%3};\n"
        : "+f"(c[0]), "+f"(c[1]), "+f"(c[2]), "+f"(c[3])
        : "r"(a[0]), "r"(a[1]), "r"(a[2]), "r"(a[3]), "r"(b[0]), "r"(b[1]));
}

// ------------------------- conversion kernels ------------------------------
// single fp16 quantization of fp32 input
__global__ __launch_bounds__(256) void quant1_kernel(
    const float* __restrict__ in, size_t ldin,
    u16* __restrict__ hi, int cols)
{
    size_t idx = (size_t)blockIdx.x * 256 + threadIdx.x;
    int cq = cols >> 2;
    size_t r  = idx / cq;
    size_t c4 = (idx % cq) * 4;
    float4 v = *(const float4*)(in + r * ldin + c4);
    *(uint2*)(hi + r * cols + c4) =
        make_uint2(packh2(v.x, v.y), packh2(v.z, v.w));
}

// per-batch 2048x2048 u16 transpose: out[z][i][m] = in[z][m][i]
__global__ __launch_bounds__(256) void transpose16_kernel(
    const u16* __restrict__ in, u16* __restrict__ outp)
{
    __shared__ u16 t[32][34];
    size_t zb = (size_t)blockIdx.z * 2048 * 2048;
    const u16* inb = in + zb;
    u16* ob = outp + zb;
    int x0 = blockIdx.x * 32, y0 = blockIdx.y * 32;
    int tx = threadIdx.x, ty = threadIdx.y;   // 32 x 8
#pragma unroll
    for (int j = 0; j < 32; j += 8)
        t[ty + j][tx] = inb[(size_t)(y0 + ty + j) * 2048 + x0 + tx];
    __syncthreads();
#pragma unroll
    for (int j = 0; j < 32; j += 8)
        ob[(size_t)(x0 + ty + j) * 2048 + y0 + tx] = t[tx][ty + j];
}

// fused softmax + fp16 quantization of a
__global__ __launch_bounds__(256) void softmax_quant_kernel(
    const float* __restrict__ s, u16* __restrict__ ah)
{
    const size_t row = blockIdx.x;
    const float* p = s + row * 2048;
    const int tid = threadIdx.x;

    float v[8];
    float mx = -1e30f;
#pragma unroll
    for (int j = 0; j < 8; j++) {
        v[j] = p[tid + j * 256];
        mx = fmaxf(mx, v[j]);
    }
    __shared__ float red[256];
    red[tid] = mx;
    __syncthreads();
#pragma unroll
    for (int st = 128; st > 0; st >>= 1) {
        if (tid < st) red[tid] = fmaxf(red[tid], red[tid + st]);
        __syncthreads();
    }
    mx = red[0];
    __syncthreads();

    float sum = 0.0f;
#pragma unroll
    for (int j = 0; j < 8; j++) {
        v[j] = __expf(v[j] - mx);
        sum += v[j];
    }
    red[tid] = sum;
    __syncthreads();
#pragma unroll
    for (int st = 128; st > 0; st >>= 1) {
        if (tid < st) red[tid] += red[tid + st];
        __syncthreads();
    }
    const float inv = 1.0f / red[0];
#pragma unroll
    for (int j = 0; j < 8; j++)
        ah[row * 2048 + tid + j * 256] = f2h(v[j] * inv);
}

// ----------------------------- GEMM kernel ---------------------------------
// Single fp16 A and B, fp32 accumulate. 4-stage cp.async ring (wait_group 2).
// MODE 0: C = alpha*acc + bias (fp32 out)
// MODE 1: fp16 out: col < 2048 -> o1[row*2048+col], else o2[row*2048+col-2048]
// MODE 2: permuted fp16 out -> o1[((rr&127)*64 + z*16 + (rr>>7))*2048 + col]
template <int MODE>
__global__ __launch_bounds__(256) void mma_gemm(
    const u16* __restrict__ A, const u16* __restrict__ B,
    float* __restrict__ C, u16* __restrict__ o1, u16* __restrict__ o2,
    int M, int N, int K,
    size_t bA, size_t bB, size_t bC,
    float alpha, const float* __restrict__ bias)
{
    extern __shared__ char smem[];
    const u32 sbase = (u32)__cvta_generic_to_shared(smem);
    const int tid = threadIdx.x, lane = tid & 31, warp = tid >> 5;
    const int wm = warp & 1, wn = warp >> 1;     // 2 x 4 warps, 64 x 32 each
    const int z = blockIdx.z;
    A += (size_t)z * bA;
    B += (size_t)z * bB;
    C += (size_t)z * bC;
    const int m0 = blockIdx.y * 128, n0 = blockIdx.x * 128;

    float acc[4][4][4];
#pragma unroll
    for (int i = 0; i < 4; i++)
#pragma unroll
        for (int j = 0; j < 4; j++)
#pragma unroll
            for (int k = 0; k < 4; k++) acc[i][j][k] = 0.0f;

    const u32 a_off = (u32)((lane & 15) * ROWB + (lane >> 4) * 16);
    const u32 b_off = (u32)(((lane & 7) + ((lane >> 4) << 3)) * ROWB +
                            ((lane >> 3) & 1) * 16);

    const int nk = K / BK;

    // per-thread fill coordinates (fixed): 512 16B chunks per array
    const int rr0 = (tid * 2) >> 2, qq0 = (tid * 2) & 3;
    const int rr1 = (tid * 2 + 1) >> 2, qq1 = (tid * 2 + 1) & 3;

    auto fill = [&](int buf, int kt) {
        u32 sb = sbase + buf * STAGE;
        int k0 = kt * BK;
        {
            size_t ga = (size_t)(m0 + rr0) * K + k0 + qq0 * 8;
            size_t gb = (size_t)(n0 + rr0) * K + k0 + qq0 * 8;
            u32 so = (u32)(rr0 * ROWB + qq0 * 16);
            cp16(sb + so, A + ga);
            cp16(sb + ARR + so, B + gb);
        }
        {
            size_t ga = (size_t)(m0 + rr1) * K + k0 + qq1 * 8;
            size_t gb = (size_t)(n0 + rr1) * K + k0 + qq1 * 8;
            u32 so = (u32)(rr1 * ROWB + qq1 * 16);
            cp16(sb + so, A + ga);
            cp16(sb + ARR + so, B + gb);
        }
        asm volatile("cp.async.commit_group;\n" ::);
    };

    // prefill NSTAGE-1 stages
#pragma unroll
    for (int i = 0; i < NSTAGE - 1; i++) fill(i, i);

    for (int kt = 0; kt < nk; kt++) {
        // stage kt complete when <= NSTAGE-2 groups outstanding
        asm volatile("cp.async.wait_group 2;\n" ::);
        __syncthreads();

        // refill ring slot (overwrites stage kt-1's buffer: safe after barrier)
        int nf = kt + NSTAGE - 1;
        if (nf < nk) fill(nf & (NSTAGE - 1), nf);
        else asm volatile("cp.async.commit_group;\n" ::);   // keep group count

        u32 sb = sbase + (kt & (NSTAGE - 1)) * STAGE;
#pragma unroll
        for (int ks = 0; ks < 2; ks++) {
            u32 bf[2][4];
#pragma unroll
            for (int np = 0; np < 2; np++) {
                u32 addr = sb + ARR +
                           (u32)((wn * 32 + np * 16) * ROWB + ks * 32) + b_off;
                ldsm4(bf[np], addr);
            }
#pragma unroll
            for (int mi = 0; mi < 4; mi++) {
                u32 af[4];
                u32 addr = sb + (u32)((wm * 64 + mi * 16) * ROWB + ks * 32) + a_off;
                ldsm4(af, addr);
#pragma unroll
                for (int ni = 0; ni < 4; ni++)
                    mma16816(acc[mi][ni], af, &bf[ni >> 1][(ni & 1) * 2]);
            }
        }
    }

    // ---- epilogue ----
#pragma unroll
    for (int mi = 0; mi < 4; mi++) {
        int row0 = m0 + wm * 64 + mi * 16 + (lane >> 2);
#pragma unroll
        for (int ni = 0; ni < 4; ni++) {
            int col = n0 + wn * 32 + ni * 8 + (lane & 3) * 2;
            float c00 = acc[mi][ni][0] * alpha, c01 = acc[mi][ni][1] * alpha;
            float c10 = acc[mi][ni][2] * alpha, c11 = acc[mi][ni][3] * alpha;

            if (MODE == 0) {
                if (bias) {
                    float b0 = bias[col], b1 = bias[col + 1];
                    c00 += b0; c01 += b1; c10 += b0; c11 += b1;
                }
                *(float2*)(C + (size_t)row0 * N + col) = make_float2(c00, c01);
                *(float2*)(C + (size_t)(row0 + 8) * N + col) = make_float2(c10, c11);
            } else if (MODE == 1) {
                // fp16-only output, split into k0 (col<2048) and v (col>=2048)
                u16* dst;
                int cc;
                if (col < 2048) { dst = o1; cc = col; }
                else            { dst = o2; cc = col - 2048; }
                *(u32*)(dst + (size_t)row0 * 2048 + cc) = packh2(c00, c01);
                *(u32*)(dst + (size_t)(row0 + 8) * 2048 + cc) = packh2(c10, c11);
            } else {  // MODE 2: permuted single fp16
                int r0 = row0, r1 = row0 + 8;
                int p0 = (r0 & 127) * 64 + z * 16 + (r0 >> 7);
                int p1 = (r1 & 127) * 64 + z * 16 + (r1 >> 7);
                *(u32*)(o1 + (size_t)p0 * 2048 + col) = packh2(c00, c01);
                *(u32*)(o1 + (size_t)p1 * 2048 + col) = packh2(c10, c11);
            }
        }
    }
}

// ------------------------------- launch ------------------------------------
extern "C" void kernel_launch(void* const* d_in, const int* in_sizes, int n_in,
                              void* d_out, int out_size)
{
    const float* x       = (const float*)d_in[0];
    const float* w_qk    = (const float*)d_in[1];
    const float* w_dense = (const float*)d_in[2];
    const float* b_dense = (const float*)d_in[3];
    float* out = (float*)d_out;

    float* s;
    u16 *xh, *wqh, *wdh, *k0u, *vh, *k0t, *vth, *ah, *qph;
    cudaGetSymbolAddress((void**)&s,   g_s);
    cudaGetSymbolAddress((void**)&xh,  g_xh);
    cudaGetSymbolAddress((void**)&wqh, g_wqh);
    cudaGetSymbolAddress((void**)&wdh, g_wdh);
    cudaGetSymbolAddress((void**)&k0u, g_k0u);
    cudaGetSymbolAddress((void**)&vh,  g_vh);
    cudaGetSymbolAddress((void**)&k0t, g_k0t);
    cudaGetSymbolAddress((void**)&vth, g_vth);
    cudaGetSymbolAddress((void**)&ah,  g_ah);
    cudaGetSymbolAddress((void**)&qph, g_qph);

    cudaFuncSetAttribute(mma_gemm<0>, cudaFuncAttributeMaxDynamicSharedMemorySize,
                         SMEM_TOTAL);
    cudaFuncSetAttribute(mma_gemm<1>, cudaFuncAttributeMaxDynamicSharedMemorySize,
                         SMEM_TOTAL);
    cudaFuncSetAttribute(mma_gemm<2>, cudaFuncAttributeMaxDynamicSharedMemorySize,
                         SMEM_TOTAL);

    const size_t BATCH = (size_t)2048 * 2048;
    const float scale = 1.0f / sqrtf((float)((double)2048 * 2047 / 2.0));

    // input quantization (all single fp16)
    quant1_kernel<<<16384, 256>>>(x,       2048, xh,  2048);
    quant1_kernel<<< 8192, 256>>>(w_qk,    2048, wqh, 2048);
    quant1_kernel<<< 4096, 256>>>(w_dense, 2048, wdh, 2048);

    // 1) kv = x @ w_qk^T ; epilogue emits fp16 k0u (cols<2048) + vh (cols>=2048)
    mma_gemm<1><<<dim3(32, 64, 1), 256, SMEM_TOTAL>>>(
        xh, wqh, nullptr, k0u, vh, 8192, 4096, 2048, 0, 0, 0, 1.0f, nullptr);

    // u16 transposes: k0u -> k0t (A of GEMM2), vh -> vth (B of GEMM4)
    transpose16_kernel<<<dim3(64, 64, 4), dim3(32, 8)>>>(k0u, k0t);
    transpose16_kernel<<<dim3(64, 64, 4), dim3(32, 8)>>>(vh,  vth);

    // 2) s = scale * k0t @ v^T  (batched)
    mma_gemm<0><<<dim3(16, 16, 4), 256, SMEM_TOTAL>>>(
        k0t, vh, s, nullptr, nullptr,
        2048, 2048, 2048, BATCH, BATCH, BATCH, scale, nullptr);

    // 3) fused softmax + fp16 quantization of a
    softmax_quant_kernel<<<8192, 256>>>(s, ah);

    // 4) q = a @ vT^T ; epilogue emits permuted fp16 q
    mma_gemm<2><<<dim3(16, 16, 4), 256, SMEM_TOTAL>>>(
        ah, vth, nullptr, qph, nullptr,
        2048, 2048, 2048, BATCH, BATCH, 0, 1.0f, nullptr);

    // 5) out = qp @ w_dense^T + bias
    mma_gemm<0><<<dim3(16, 64, 1), 256, SMEM_TOTAL>>>(
        qph, wdh, out, nullptr, nullptr,
        8192, 2048, 2048, 0, 0, 0, 1.0f, b_dense);
}